// round 17
// baseline (speedup 1.0000x reference)
#include <cuda_runtime.h>
#include <cuda_fp16.h>
#include <math.h>
#include <stdint.h>

// Problem constants
#define NTOK   4096      // B*S = 2*2048
#define DMODEL 1024
#define DFF    4096
#define NHEAD  16
#define HD     64
#define SEQ    2048
#define QLD    (3 * DMODEL)   // fused qkv row stride

// ---------------------------------------------------------------------------
// Scratch (static device globals; no runtime allocation allowed)
// ---------------------------------------------------------------------------
__device__ __align__(16) __half g_qkvh[NTOK * 3 * DMODEL];    // fused q|k|v half
__device__ __align__(16) __half g_srcr[NTOK * DMODEL];        // half src (QKV A)
__device__ __align__(16) __half g_xr  [NTOK * DMODEL];        // half LN1 out (FFN1 A)
__device__ __align__(16) __half g_wqkvT[3 * DMODEL * DMODEL]; // [3072,1024] K-major half
__device__ __align__(16) __half g_woT [DMODEL * DMODEL];
__device__ __align__(16) __half g_w1T [DFF * DMODEL];
__device__ __align__(16) __half g_w2T [DMODEL * DFF];
__device__ __align__(16) float  g_bqkv[3 * DMODEL];
__device__ __align__(16) __half g_ctx [NTOK * DMODEL];        // half flash output (O-proj A)
__device__ __align__(16) float  g_tmp [NTOK * DMODEL];
__device__ __align__(16) float  g_x   [NTOK * DMODEL];
__device__ __align__(16) __half g_ff  [NTOK * DFF];           // half FFN1 output (FFN2 A)

// ---------------------------------------------------------------------------
// PTX helpers
// ---------------------------------------------------------------------------
__device__ __forceinline__ uint32_t smem_u32(const void* p) {
    uint32_t a;
    asm("{ .reg .u64 t; cvta.to.shared.u64 t, %1; cvt.u32.u64 %0, t; }" : "=r"(a) : "l"(p));
    return a;
}
#define CP_ASYNC16(dst, src) \
    asm volatile("cp.async.cg.shared.global [%0], [%1], 16;" :: "r"(dst), "l"(src))
#define CP_COMMIT() asm volatile("cp.async.commit_group;" ::: "memory")
#define CP_WAIT(n)  asm volatile("cp.async.wait_group %0;" :: "n"(n) : "memory")

#define LDMATRIX_X4(r0, r1, r2, r3, addr) \
    asm volatile("ldmatrix.sync.aligned.m8n8.x4.shared.b16 {%0,%1,%2,%3}, [%4];" \
                 : "=r"(r0), "=r"(r1), "=r"(r2), "=r"(r3) : "r"(addr))

#define LDMATRIX_X4_TRANS(r0, r1, r2, r3, addr) \
    asm volatile("ldmatrix.sync.aligned.m8n8.x4.trans.shared.b16 {%0,%1,%2,%3}, [%4];" \
                 : "=r"(r0), "=r"(r1), "=r"(r2), "=r"(r3) : "r"(addr))

#define MMA_F16(c0, c1, c2, c3, a0, a1, a2, a3, b0, b1) \
    asm volatile("mma.sync.aligned.m16n8k16.row.col.f32.f16.f16.f32 " \
                 "{%0,%1,%2,%3}, {%4,%5,%6,%7}, {%8,%9}, {%0,%1,%2,%3};" \
                 : "+f"(c0), "+f"(c1), "+f"(c2), "+f"(c3) \
                 : "r"(a0), "r"(a1), "r"(a2), "r"(a3), "r"(b0), "r"(b1))

__device__ __forceinline__ uint32_t packh2(float x, float y) {
    __half2 h = __floats2half2_rn(x, y);
    return *(uint32_t*)&h;
}

// ---------------------------------------------------------------------------
// fp16 GEMM, wide variant: 256x128 tile, 512 threads (16 warps, warp 64x32),
// 3-stage cp.async, A-fragment 2-deep ring.  OUTM: 0 = fp32, 2 = half.
// ---------------------------------------------------------------------------
#define STAGES 3
#define A_ST_BYTES (256 * 128)
#define B_ST_BYTES (128 * 128)
#define STAGE_BYTES (A_ST_BYTES + B_ST_BYTES)
#define SMEM_DYN (STAGES * STAGE_BYTES)      // 144KB

template <bool RELU, int OUTM>
__global__ __launch_bounds__(512, 1)
void gemm_mma(const __half* __restrict__ A, const __half* __restrict__ BT,
              const float* __restrict__ bias, void* __restrict__ Cv,
              int M, int N, int K)
{
    extern __shared__ char smem[];
    const uint32_t sbase = smem_u32(smem);
    const int tid  = threadIdx.x;
    const int wid  = tid >> 5;
    const int lane = tid & 31;
    const int warp_m = wid & 3;
    const int warp_n = wid >> 2;
    const int gid = lane >> 2;
    const int tg  = lane & 3;

    const int bm = blockIdx.y * 256;
    const int bn = blockIdx.x * 128;
    const int KT = K >> 6;

    const int arow = tid >> 1;
    const int au0  = (tid & 1) * 4;
    const __half* Ag = A + (size_t)(bm + arow) * K + au0 * 8;
    uint32_t aswz[4];
    #pragma unroll
    for (int i = 0; i < 4; i++) {
        uint32_t off = arow * 128 + (au0 + i) * 16;
        aswz[i] = off ^ ((off >> 3) & 0x70);
    }
    const int brow = tid >> 2;
    const int bu0  = (tid & 3) * 2;
    const __half* Bg = BT + (size_t)(bn + brow) * K + bu0 * 8;
    uint32_t bswz[2];
    #pragma unroll
    for (int i = 0; i < 2; i++) {
        uint32_t off = brow * 128 + (bu0 + i) * 16;
        bswz[i] = off ^ ((off >> 3) & 0x70);
    }

    uint32_t a_rel[4], a_xr[4];
    #pragma unroll
    for (int i = 0; i < 4; i++) {
        int r = warp_m * 64 + i * 16 + (lane & 7) + ((lane >> 3) & 1) * 8;
        a_rel[i] = r * 128;
        a_xr[i]  = (r & 7) << 4;
    }
    const uint32_t a_kb = ((lane >> 4) & 1) * 16;
    uint32_t b_rel[2], b_xr[2];
    #pragma unroll
    for (int j = 0; j < 2; j++) {
        int r = warp_n * 32 + j * 16 + (lane & 7) + ((lane >> 4) & 1) * 8;
        b_rel[j] = r * 128;
        b_xr[j]  = (r & 7) << 4;
    }
    const uint32_t b_kb = ((lane >> 3) & 1) * 16;

    float acc[4][4][4];
    #pragma unroll
    for (int i = 0; i < 4; i++)
        #pragma unroll
        for (int t = 0; t < 4; t++)
            #pragma unroll
            for (int r = 0; r < 4; r++) acc[i][t][r] = 0.f;

    auto load_tile = [&](int s, int kt) {
        const uint32_t sA = sbase + s * STAGE_BYTES;
        const uint32_t sB = sA + A_ST_BYTES;
        const __half* ar = Ag + kt * 64;
        const __half* br = Bg + kt * 64;
        #pragma unroll
        for (int i = 0; i < 4; i++) CP_ASYNC16(sA + aswz[i], ar + i * 8);
        #pragma unroll
        for (int i = 0; i < 2; i++) CP_ASYNC16(sB + bswz[i], br + i * 8);
    };

    #pragma unroll
    for (int s = 0; s < STAGES - 1; s++) { load_tile(s, s); CP_COMMIT(); }

    int cur = 0, pfs = STAGES - 1;
    for (int kt = 0; kt < KT; kt++) {
        CP_WAIT(STAGES - 2);
        __syncthreads();

        const int pf = kt + STAGES - 1;
        if (pf < KT) load_tile(pfs, pf);
        CP_COMMIT();

        const uint32_t sA = sbase + cur * STAGE_BYTES;
        const uint32_t sB = sA + A_ST_BYTES;

        #pragma unroll
        for (int ks = 0; ks < 4; ks++) {
            const uint32_t kso = ks * 32;
            uint32_t bf[4][2];
            #pragma unroll
            for (int j = 0; j < 2; j++) {
                uint32_t r0, r1, r2, r3;
                uint32_t addr = sB + ((b_rel[j] + b_kb + kso) ^ b_xr[j]);
                LDMATRIX_X4(r0, r1, r2, r3, addr);
                bf[2*j+0][0] = r0; bf[2*j+0][1] = r1;
                bf[2*j+1][0] = r2; bf[2*j+1][1] = r3;
            }
            uint32_t af[2][4];
            {
                uint32_t addr = sA + ((a_rel[0] + a_kb + kso) ^ a_xr[0]);
                LDMATRIX_X4(af[0][0], af[0][1], af[0][2], af[0][3], addr);
            }
            #pragma unroll
            for (int i = 0; i < 4; i++) {
                if (i < 3) {
                    uint32_t addr = sA + ((a_rel[i+1] + a_kb + kso) ^ a_xr[i+1]);
                    LDMATRIX_X4(af[(i+1)&1][0], af[(i+1)&1][1],
                                af[(i+1)&1][2], af[(i+1)&1][3], addr);
                }
                const uint32_t* a = af[i & 1];
                #pragma unroll
                for (int t = 0; t < 4; t++)
                    MMA_F16(acc[i][t][0], acc[i][t][1], acc[i][t][2], acc[i][t][3],
                            a[0], a[1], a[2], a[3], bf[t][0], bf[t][1]);
            }
        }
        cur++; if (cur == STAGES) cur = 0;
        pfs++; if (pfs == STAGES) pfs = 0;
    }

    #pragma unroll
    for (int i = 0; i < 4; i++) {
        const int row0 = bm + warp_m * 64 + i * 16 + gid;
        #pragma unroll
        for (int t = 0; t < 4; t++) {
            const int col = bn + warp_n * 32 + t * 8 + 2 * tg;
            const float2 bv = *(const float2*)(bias + col);
            float2 v0, v1;
            v0.x = acc[i][t][0] + bv.x; v0.y = acc[i][t][1] + bv.y;
            v1.x = acc[i][t][2] + bv.x; v1.y = acc[i][t][3] + bv.y;
            if (RELU) {
                v0.x = fmaxf(v0.x, 0.f); v0.y = fmaxf(v0.y, 0.f);
                v1.x = fmaxf(v1.x, 0.f); v1.y = fmaxf(v1.y, 0.f);
            }
            if (OUTM == 2) {
                __half* Ch = (__half*)Cv;
                *(__half2*)(Ch + (size_t)row0 * N + col)       = __floats2half2_rn(v0.x, v0.y);
                *(__half2*)(Ch + (size_t)(row0 + 8) * N + col) = __floats2half2_rn(v1.x, v1.y);
            } else {
                float* Cf = (float*)Cv;
                *(float2*)(Cf + (size_t)row0 * N + col)       = v0;
                *(float2*)(Cf + (size_t)(row0 + 8) * N + col) = v1;
            }
        }
    }
}

// ---------------------------------------------------------------------------
// fp16 GEMM, narrow variant (R12-proven): 128x128 tile, 256 threads (8 warps,
// warp 64x32), 3-stage cp.async, 2 blocks/SM. For N=1024 GEMMs (2x the blocks).
// ---------------------------------------------------------------------------
#define STAGE128_BYTES (2 * 128 * 128)       // A 16KB + B 16KB
#define SMEM_DYN128 (STAGES * STAGE128_BYTES) // 96KB -> 2 blocks/SM

template <bool RELU, int OUTM>
__global__ __launch_bounds__(256, 2)
void gemm_mma128(const __half* __restrict__ A, const __half* __restrict__ BT,
                 const float* __restrict__ bias, void* __restrict__ Cv,
                 int M, int N, int K)
{
    extern __shared__ char smem[];
    const uint32_t sbase = smem_u32(smem);
    const int tid  = threadIdx.x;
    const int wid  = tid >> 5;
    const int lane = tid & 31;
    const int warp_m = wid & 1;
    const int warp_n = wid >> 1;
    const int gid = lane >> 2;
    const int tg  = lane & 3;

    const int bm = blockIdx.y * 128;
    const int bn = blockIdx.x * 128;
    const int KT = K >> 6;

    const int lrow  = tid >> 1;
    const int lunit = (tid & 1) * 4;
    const __half* Ag = A  + (size_t)(bm + lrow) * K + lunit * 8;
    const __half* Bg = BT + (size_t)(bn + lrow) * K + lunit * 8;
    uint32_t lsw[4];
    #pragma unroll
    for (int i = 0; i < 4; i++) {
        uint32_t off = lrow * 128 + (lunit + i) * 16;
        lsw[i] = off ^ ((off >> 3) & 0x70);
    }

    uint32_t a_rel[4], a_xr[4];
    #pragma unroll
    for (int i = 0; i < 4; i++) {
        int r = warp_m * 64 + i * 16 + (lane & 7) + ((lane >> 3) & 1) * 8;
        a_rel[i] = r * 128;
        a_xr[i]  = (r & 7) << 4;
    }
    const uint32_t a_kb = ((lane >> 4) & 1) * 16;
    uint32_t b_rel[2], b_xr[2];
    #pragma unroll
    for (int j = 0; j < 2; j++) {
        int r = warp_n * 32 + j * 16 + (lane & 7) + ((lane >> 4) & 1) * 8;
        b_rel[j] = r * 128;
        b_xr[j]  = (r & 7) << 4;
    }
    const uint32_t b_kb = ((lane >> 3) & 1) * 16;

    float acc[4][4][4];
    #pragma unroll
    for (int i = 0; i < 4; i++)
        #pragma unroll
        for (int t = 0; t < 4; t++)
            #pragma unroll
            for (int r = 0; r < 4; r++) acc[i][t][r] = 0.f;

    auto load_tile = [&](int s, int kt) {
        const uint32_t sA = sbase + s * STAGE128_BYTES;
        const uint32_t sB = sA + 16384;
        const __half* ar = Ag + kt * 64;
        const __half* br = Bg + kt * 64;
        #pragma unroll
        for (int i = 0; i < 4; i++) CP_ASYNC16(sA + lsw[i], ar + i * 8);
        #pragma unroll
        for (int i = 0; i < 4; i++) CP_ASYNC16(sB + lsw[i], br + i * 8);
    };

    #pragma unroll
    for (int s = 0; s < STAGES - 1; s++) { load_tile(s, s); CP_COMMIT(); }

    int cur = 0, pfs = STAGES - 1;
    for (int kt = 0; kt < KT; kt++) {
        CP_WAIT(STAGES - 2);
        __syncthreads();

        const int pf = kt + STAGES - 1;
        if (pf < KT) load_tile(pfs, pf);
        CP_COMMIT();

        const uint32_t sA = sbase + cur * STAGE128_BYTES;
        const uint32_t sB = sA + 16384;

        #pragma unroll
        for (int ks = 0; ks < 4; ks++) {
            const uint32_t kso = ks * 32;
            uint32_t bf[4][2];
            #pragma unroll
            for (int j = 0; j < 2; j++) {
                uint32_t r0, r1, r2, r3;
                uint32_t addr = sB + ((b_rel[j] + b_kb + kso) ^ b_xr[j]);
                LDMATRIX_X4(r0, r1, r2, r3, addr);
                bf[2*j+0][0] = r0; bf[2*j+0][1] = r1;
                bf[2*j+1][0] = r2; bf[2*j+1][1] = r3;
            }
            uint32_t af[2][4];
            {
                uint32_t addr = sA + ((a_rel[0] + a_kb + kso) ^ a_xr[0]);
                LDMATRIX_X4(af[0][0], af[0][1], af[0][2], af[0][3], addr);
            }
            #pragma unroll
            for (int i = 0; i < 4; i++) {
                if (i < 3) {
                    uint32_t addr = sA + ((a_rel[i+1] + a_kb + kso) ^ a_xr[i+1]);
                    LDMATRIX_X4(af[(i+1)&1][0], af[(i+1)&1][1],
                                af[(i+1)&1][2], af[(i+1)&1][3], addr);
                }
                const uint32_t* a = af[i & 1];
                #pragma unroll
                for (int t = 0; t < 4; t++)
                    MMA_F16(acc[i][t][0], acc[i][t][1], acc[i][t][2], acc[i][t][3],
                            a[0], a[1], a[2], a[3], bf[t][0], bf[t][1]);
            }
        }
        cur++; if (cur == STAGES) cur = 0;
        pfs++; if (pfs == STAGES) pfs = 0;
    }

    #pragma unroll
    for (int i = 0; i < 4; i++) {
        const int row0 = bm + warp_m * 64 + i * 16 + gid;
        #pragma unroll
        for (int t = 0; t < 4; t++) {
            const int col = bn + warp_n * 32 + t * 8 + 2 * tg;
            const float2 bv = *(const float2*)(bias + col);
            float2 v0, v1;
            v0.x = acc[i][t][0] + bv.x; v0.y = acc[i][t][1] + bv.y;
            v1.x = acc[i][t][2] + bv.x; v1.y = acc[i][t][3] + bv.y;
            if (RELU) {
                v0.x = fmaxf(v0.x, 0.f); v0.y = fmaxf(v0.y, 0.f);
                v1.x = fmaxf(v1.x, 0.f); v1.y = fmaxf(v1.y, 0.f);
            }
            if (OUTM == 2) {
                __half* Ch = (__half*)Cv;
                *(__half2*)(Ch + (size_t)row0 * N + col)       = __floats2half2_rn(v0.x, v0.y);
                *(__half2*)(Ch + (size_t)(row0 + 8) * N + col) = __floats2half2_rn(v1.x, v1.y);
            } else {
                float* Cf = (float*)Cv;
                *(float2*)(Cf + (size_t)row0 * N + col)       = v0;
                *(float2*)(Cf + (size_t)(row0 + 8) * N + col) = v1;
            }
        }
    }
}

// ---------------------------------------------------------------------------
// fp16 tensor-core flash attention (R14-proven). 128 queries x 1 head, 8 warps.
// ---------------------------------------------------------------------------
#define ATT_SMEM 49152   // 2 stages x (8KB K + 8KB V) + 16KB Q

__global__ __launch_bounds__(256, 2)
void flash_mma(const __half* __restrict__ QKV, __half* __restrict__ O)
{
    extern __shared__ char smem[];
    const uint32_t sbase = smem_u32(smem);
    const int tid  = threadIdx.x;
    const int wid  = tid >> 5;
    const int lane = tid & 31;
    const int gid  = lane >> 2;
    const int tg   = lane & 3;

    const int bh = blockIdx.y;
    const int b  = bh >> 4;
    const int h  = bh & 15;
    const int q0 = blockIdx.x * 128;

    const __half* Qg = QKV + (size_t)b * SEQ * QLD + h * HD;
    const __half* Kg = Qg + DMODEL;
    const __half* Vg = Qg + 2 * DMODEL;

    const uint32_t qreg = sbase + 32768;

    const int qrow = tid >> 1;
    const int qu0  = (tid & 1) * 4;
    uint32_t qsw[4];
    #pragma unroll
    for (int i = 0; i < 4; i++) {
        uint32_t off = qrow * 128 + (qu0 + i) * 16;
        qsw[i] = off ^ ((off >> 3) & 0x70);
    }
    const int krow = tid >> 2;
    const int ku0  = (tid & 3) * 2;
    uint32_t kvsw[2];
    #pragma unroll
    for (int i = 0; i < 2; i++) {
        uint32_t off = krow * 128 + (ku0 + i) * 16;
        kvsw[i] = off ^ ((off >> 3) & 0x70);
    }

    uint32_t aq_rel, aq_xr;
    {
        int r = wid * 16 + (lane & 7) + ((lane >> 3) & 1) * 8;
        aq_rel = r * 128;
        aq_xr  = (r & 7) << 4;
    }
    const uint32_t a_kb = ((lane >> 4) & 1) * 16;
    uint32_t b_rel[4], b_xr[4];
    #pragma unroll
    for (int j = 0; j < 4; j++) {
        int r = j * 16 + (lane & 7) + ((lane >> 4) & 1) * 8;
        b_rel[j] = r * 128;
        b_xr[j]  = (r & 7) << 4;
    }
    const uint32_t b_kb = ((lane >> 3) & 1) * 16;
    uint32_t v_rel[4];
    #pragma unroll
    for (int j = 0; j < 4; j++) {
        int kr = ((lane >> 3) & 1) * 8 + (lane & 7);
        int dc = j * 16 + ((lane >> 4) & 1) * 8;
        v_rel[j] = kr * 128 + dc * 2;
    }

    auto load_KV = [&](int stage, int kt) {
        const uint32_t sK = sbase + stage * 16384;
        const uint32_t sV = sK + 8192;
        const __half* kr = Kg + (size_t)(kt * 64 + krow) * QLD + ku0 * 8;
        const __half* vr = Vg + (size_t)(kt * 64 + krow) * QLD + ku0 * 8;
        #pragma unroll
        for (int i = 0; i < 2; i++) CP_ASYNC16(sK + kvsw[i], kr + i * 8);
        #pragma unroll
        for (int i = 0; i < 2; i++) CP_ASYNC16(sV + kvsw[i], vr + i * 8);
    };

    {
        const __half* qr = Qg + (size_t)(q0 + qrow) * QLD + qu0 * 8;
        #pragma unroll
        for (int i = 0; i < 4; i++) CP_ASYNC16(qreg + qsw[i], qr + i * 8);
        load_KV(0, 0);
        CP_COMMIT();
        CP_WAIT(0);
        __syncthreads();
    }

    uint32_t qf[4][4];
    #pragma unroll
    for (int ks = 0; ks < 4; ks++) {
        uint32_t addr = qreg + ((aq_rel + a_kb + ks * 32) ^ aq_xr);
        LDMATRIX_X4(qf[ks][0], qf[ks][1], qf[ks][2], qf[ks][3], addr);
    }
    __syncthreads();

    const int NT = SEQ / 64;
    load_KV(1, 1);
    CP_COMMIT();

    float o[8][4];
    #pragma unroll
    for (int t = 0; t < 8; t++)
        #pragma unroll
        for (int r = 0; r < 4; r++) o[t][r] = 0.f;
    float m0 = -1e30f, m1 = -1e30f, l0 = 0.f, l1 = 0.f;

    for (int kt = 0; kt < NT; kt++) {
        if (kt < NT - 1) { CP_WAIT(1); } else { CP_WAIT(0); }
        __syncthreads();
        const uint32_t sK = sbase + (kt & 1) * 16384;
        const uint32_t sV = sK + 8192;

        float s[8][4];
        #pragma unroll
        for (int t = 0; t < 8; t++)
            #pragma unroll
            for (int r = 0; r < 4; r++) s[t][r] = 0.f;

        #pragma unroll
        for (int ks = 0; ks < 4; ks++) {
            uint32_t bf[8][2];
            #pragma unroll
            for (int j = 0; j < 4; j++) {
                uint32_t r0, r1, r2, r3;
                uint32_t addr = sK + ((b_rel[j] + b_kb + ks * 32) ^ b_xr[j]);
                LDMATRIX_X4(r0, r1, r2, r3, addr);
                bf[2*j+0][0] = r0; bf[2*j+0][1] = r1;
                bf[2*j+1][0] = r2; bf[2*j+1][1] = r3;
            }
            const uint32_t* aq = qf[ks];
            #pragma unroll
            for (int t = 0; t < 8; t++)
                MMA_F16(s[t][0], s[t][1], s[t][2], s[t][3],
                        aq[0], aq[1], aq[2], aq[3], bf[t][0], bf[t][1]);
        }

        float tmax0 = -1e30f, tmax1 = -1e30f;
        #pragma unroll
        for (int t = 0; t < 8; t++) {
            s[t][0] *= 0.125f; s[t][1] *= 0.125f; s[t][2] *= 0.125f; s[t][3] *= 0.125f;
            tmax0 = fmaxf(tmax0, fmaxf(s[t][0], s[t][1]));
            tmax1 = fmaxf(tmax1, fmaxf(s[t][2], s[t][3]));
        }
        tmax0 = fmaxf(tmax0, __shfl_xor_sync(0xffffffffu, tmax0, 1));
        tmax0 = fmaxf(tmax0, __shfl_xor_sync(0xffffffffu, tmax0, 2));
        tmax1 = fmaxf(tmax1, __shfl_xor_sync(0xffffffffu, tmax1, 1));
        tmax1 = fmaxf(tmax1, __shfl_xor_sync(0xffffffffu, tmax1, 2));

        const float mnew0 = fmaxf(m0, tmax0);
        const float mnew1 = fmaxf(m1, tmax1);
        const float corr0 = __expf(m0 - mnew0);
        const float corr1 = __expf(m1 - mnew1);

        float rs0 = 0.f, rs1 = 0.f;
        #pragma unroll
        for (int t = 0; t < 8; t++) {
            s[t][0] = __expf(s[t][0] - mnew0);
            s[t][1] = __expf(s[t][1] - mnew0);
            s[t][2] = __expf(s[t][2] - mnew1);
            s[t][3] = __expf(s[t][3] - mnew1);
            rs0 += s[t][0] + s[t][1];
            rs1 += s[t][2] + s[t][3];
        }
        rs0 += __shfl_xor_sync(0xffffffffu, rs0, 1);
        rs0 += __shfl_xor_sync(0xffffffffu, rs0, 2);
        rs1 += __shfl_xor_sync(0xffffffffu, rs1, 1);
        rs1 += __shfl_xor_sync(0xffffffffu, rs1, 2);

        l0 = l0 * corr0 + rs0;
        l1 = l1 * corr1 + rs1;
        #pragma unroll
        for (int t = 0; t < 8; t++) {
            o[t][0] *= corr0; o[t][1] *= corr0;
            o[t][2] *= corr1; o[t][3] *= corr1;
        }
        m0 = mnew0; m1 = mnew1;

        #pragma unroll
        for (int ks = 0; ks < 4; ks++) {
            uint32_t a0 = packh2(s[2*ks+0][0], s[2*ks+0][1]);
            uint32_t a1 = packh2(s[2*ks+0][2], s[2*ks+0][3]);
            uint32_t a2 = packh2(s[2*ks+1][0], s[2*ks+1][1]);
            uint32_t a3 = packh2(s[2*ks+1][2], s[2*ks+1][3]);

            uint32_t bf[8][2];
            #pragma unroll
            for (int j = 0; j < 4; j++) {
                uint32_t r0, r1, r2, r3;
                uint32_t off = v_rel[j] + ks * 2048;
                uint32_t addr = sV + (off ^ ((off >> 3) & 0x70));
                LDMATRIX_X4_TRANS(r0, r1, r2, r3, addr);
                bf[2*j+0][0] = r0; bf[2*j+0][1] = r1;
                bf[2*j+1][0] = r2; bf[2*j+1][1] = r3;
            }
            #pragma unroll
            for (int t = 0; t < 8; t++)
                MMA_F16(o[t][0], o[t][1], o[t][2], o[t][3],
                        a0, a1, a2, a3, bf[t][0], bf[t][1]);
        }

        __syncthreads();
        const int pf = kt + 2;
        if (pf < NT) { load_KV(pf & 1, pf); CP_COMMIT(); }
    }

    const float inv0 = 1.0f / l0;
    const float inv1 = 1.0f / l1;
    const int qa = q0 + wid * 16 + gid;
    __half* orow0 = O + (size_t)(b * SEQ + qa)     * DMODEL + h * HD;
    __half* orow1 = O + (size_t)(b * SEQ + qa + 8) * DMODEL + h * HD;
    #pragma unroll
    for (int t = 0; t < 8; t++) {
        const int col = t * 8 + 2 * tg;
        *(__half2*)(orow0 + col) = __floats2half2_rn(o[t][0] * inv0, o[t][1] * inv0);
        *(__half2*)(orow1 + col) = __floats2half2_rn(o[t][2] * inv1, o[t][3] * inv1);
    }
}

// ---------------------------------------------------------------------------
// Fused preprocessing: weight transposes + src half-copy + bias concat, ONE launch.
// ---------------------------------------------------------------------------
__device__ __forceinline__ void tr64(const float* __restrict__ in,
                                     __half* __restrict__ out,
                                     int K, int N, int kt, int nt)
{
    __shared__ float tile[64][65];
    const int t  = threadIdx.x;
    const int r  = t >> 2;
    const int c0 = (t & 3) * 16;

    const float* ip = in + (size_t)(kt * 64 + r) * N + nt * 64 + c0;
    #pragma unroll
    for (int i = 0; i < 4; i++) {
        float4 v = *(const float4*)(ip + i * 4);
        tile[r][c0 + 4*i + 0] = v.x;
        tile[r][c0 + 4*i + 1] = v.y;
        tile[r][c0 + 4*i + 2] = v.z;
        tile[r][c0 + 4*i + 3] = v.w;
    }
    __syncthreads();

    __align__(16) __half2 hb[8];
    #pragma unroll
    for (int j = 0; j < 8; j++)
        hb[j] = __floats2half2_rn(tile[c0 + 2*j][r], tile[c0 + 2*j + 1][r]);

    __half* op = out + (size_t)(nt * 64 + r) * K + kt * 64 + c0;
    *(uint4*)(op)     = ((uint4*)hb)[0];
    *(uint4*)(op + 8) = ((uint4*)hb)[1];
}

__global__ __launch_bounds__(256)
void prep_all(const float* __restrict__ src,
              const float* __restrict__ Wq, const float* __restrict__ Wk,
              const float* __restrict__ Wv, const float* __restrict__ Wo,
              const float* __restrict__ W1, const float* __restrict__ W2,
              const float* __restrict__ bq, const float* __restrict__ bk,
              const float* __restrict__ bv,
              __half* __restrict__ srcr,
              __half* __restrict__ wqkvT, __half* __restrict__ woT,
              __half* __restrict__ w1T,   __half* __restrict__ w2T,
              float* __restrict__ bqkv)
{
    const int id = blockIdx.x;
    if (id < 1024) {
        const int w = id >> 8, rr = id & 255;
        const float* in = (w == 0) ? Wq : (w == 1) ? Wk : (w == 2) ? Wv : Wo;
        __half* out = (w < 3) ? (wqkvT + (size_t)w * DMODEL * DMODEL) : woT;
        tr64(in, out, DMODEL, DMODEL, rr >> 4, rr & 15);
    } else if (id < 2048) {
        const int rr = id - 1024;
        tr64(W1, w1T, DMODEL, DFF, rr >> 6, rr & 63);
    } else if (id < 3072) {
        const int rr = id - 2048;
        tr64(W2, w2T, DFF, DMODEL, rr >> 4, rr & 15);
    } else if (id < 3072 + 4096) {
        int i = (id - 3072) * 256 + threadIdx.x;
        float4 v = ((const float4*)src)[i];
        __half2* o = (__half2*)srcr + i * 2;
        o[0] = __floats2half2_rn(v.x, v.y);
        o[1] = __floats2half2_rn(v.z, v.w);
    } else {
        int i = (id - 3072 - 4096) * 256 + threadIdx.x;
        if (i < DMODEL)            bqkv[i] = bq[i];
        else if (i < 2 * DMODEL)   bqkv[i] = bk[i - DMODEL];
        else if (i < 3 * DMODEL)   bqkv[i] = bv[i - 2 * DMODEL];
    }
}

// ---------------------------------------------------------------------------
// Fused residual add + LayerNorm. Optionally writes a half copy for fp16 GEMM A.
// ---------------------------------------------------------------------------
__global__ __launch_bounds__(256)
void add_ln(const float* __restrict__ A, const float* __restrict__ Bv,
            const float* __restrict__ g, const float* __restrict__ be,
            float* __restrict__ out, __half* __restrict__ out_h)
{
    const int row = blockIdx.x;
    const int tid = threadIdx.x;

    const float4 a4 = ((const float4*)(A  + (size_t)row * DMODEL))[tid];
    const float4 b4 = ((const float4*)(Bv + (size_t)row * DMODEL))[tid];
    float4 v;
    v.x = a4.x + b4.x; v.y = a4.y + b4.y; v.z = a4.z + b4.z; v.w = a4.w + b4.w;

    float s  = v.x + v.y + v.z + v.w;
    float ss = v.x*v.x + v.y*v.y + v.z*v.z + v.w*v.w;

    #pragma unroll
    for (int ofs = 16; ofs > 0; ofs >>= 1) {
        s  += __shfl_xor_sync(0xFFFFFFFFu, s,  ofs);
        ss += __shfl_xor_sync(0xFFFFFFFFu, ss, ofs);
    }

    __shared__ float shs[8], shss[8];
    const int w = tid >> 5;
    if ((tid & 31) == 0) { shs[w] = s; shss[w] = ss; }
    __syncthreads();
    if (tid < 32) {
        float s2  = (tid < 8) ? shs[tid]  : 0.f;
        float ss2 = (tid < 8) ? shss[tid] : 0.f;
        #pragma unroll
        for (int ofs = 4; ofs > 0; ofs >>= 1) {
            s2  += __shfl_xor_sync(0xFFFFFFFFu, s2,  ofs);
            ss2 += __shfl_xor_sync(0xFFFFFFFFu, ss2, ofs);
        }
        if (tid == 0) { shs[0] = s2; shss[0] = ss2; }
    }
    __syncthreads();

    const float mu  = shs[0]  * (1.f / DMODEL);
    const float var = shss[0] * (1.f / DMODEL) - mu * mu;
    const float inv = rsqrtf(var + 1e-5f);

    const float4 gv = ((const float4*)g)[tid];
    const float4 bb = ((const float4*)be)[tid];
    float4 o;
    o.x = (v.x - mu) * inv * gv.x + bb.x;
    o.y = (v.y - mu) * inv * gv.y + bb.y;
    o.z = (v.z - mu) * inv * gv.z + bb.z;
    o.w = (v.w - mu) * inv * gv.w + bb.w;
    ((float4*)(out + (size_t)row * DMODEL))[tid] = o;
    if (out_h) {
        __half2* oh = (__half2*)(out_h + (size_t)row * DMODEL) + tid * 2;
        oh[0] = __floats2half2_rn(o.x, o.y);
        oh[1] = __floats2half2_rn(o.z, o.w);
    }
}

// ---------------------------------------------------------------------------
// Launch
// ---------------------------------------------------------------------------
extern "C" void kernel_launch(void* const* d_in, const int* in_sizes, int n_in,
                              void* d_out, int out_size)
{
    const float* src  = (const float*)d_in[0];
    const float* Wq   = (const float*)d_in[1];
    const float* bq   = (const float*)d_in[2];
    const float* Wk   = (const float*)d_in[3];
    const float* bk   = (const float*)d_in[4];
    const float* Wv   = (const float*)d_in[5];
    const float* bv   = (const float*)d_in[6];
    const float* Wo   = (const float*)d_in[7];
    const float* bo   = (const float*)d_in[8];
    const float* W1   = (const float*)d_in[9];
    const float* b1   = (const float*)d_in[10];
    const float* W2   = (const float*)d_in[11];
    const float* b2   = (const float*)d_in[12];
    const float* ln1g = (const float*)d_in[13];
    const float* ln1b = (const float*)d_in[14];
    const float* ln2g = (const float*)d_in[15];
    const float* ln2b = (const float*)d_in[16];
    float* out = (float*)d_out;

    float  *pbqkv, *ptmp, *px;
    __half *pqkvh, *psrcr, *pxr, *pwqkvT, *pwoT, *pw1T, *pw2T, *pctx, *pff;
    cudaGetSymbolAddress((void**)&pqkvh,  g_qkvh);
    cudaGetSymbolAddress((void**)&psrcr,  g_srcr);
    cudaGetSymbolAddress((void**)&pxr,    g_xr);
    cudaGetSymbolAddress((void**)&pwqkvT, g_wqkvT);
    cudaGetSymbolAddress((void**)&pwoT,   g_woT);
    cudaGetSymbolAddress((void**)&pw1T,   g_w1T);
    cudaGetSymbolAddress((void**)&pw2T,   g_w2T);
    cudaGetSymbolAddress((void**)&pbqkv,  g_bqkv);
    cudaGetSymbolAddress((void**)&pctx,   g_ctx);
    cudaGetSymbolAddress((void**)&ptmp,   g_tmp);
    cudaGetSymbolAddress((void**)&px,     g_x);
    cudaGetSymbolAddress((void**)&pff,    g_ff);

    cudaFuncSetAttribute((const void*)gemm_mma<false,2>,    cudaFuncAttributeMaxDynamicSharedMemorySize, SMEM_DYN);
    cudaFuncSetAttribute((const void*)gemm_mma<true,2>,     cudaFuncAttributeMaxDynamicSharedMemorySize, SMEM_DYN);
    cudaFuncSetAttribute((const void*)gemm_mma128<false,0>, cudaFuncAttributeMaxDynamicSharedMemorySize, SMEM_DYN128);
    cudaFuncSetAttribute((const void*)flash_mma, cudaFuncAttributeMaxDynamicSharedMemorySize, ATT_SMEM);

    // All preprocessing in one launch
    prep_all<<<3072 + 4096 + 12, 256>>>(src, Wq, Wk, Wv, Wo, W1, W2, bq, bk, bv,
                                        psrcr, pwqkvT, pwoT, pw1T, pw2T, pbqkv);

    // Fused QKV projection (wide variant; half out)
    gemm_mma<false, 2><<<dim3(3 * DMODEL / 128, NTOK / 256), 512, SMEM_DYN>>>(
        psrcr, pwqkvT, pbqkv, pqkvh, NTOK, 3 * DMODEL, DMODEL);

    // fp16 flash attention (128 queries/block; V via trans ldmatrix; half ctx out)
    flash_mma<<<dim3(SEQ / 128, 2 * NHEAD), 256, ATT_SMEM>>>(pqkvh, pctx);

    // Output projection (narrow variant: 256 blocks, 2/SM) + LN1
    gemm_mma128<false, 0><<<dim3(DMODEL / 128, NTOK / 128), 256, SMEM_DYN128>>>(
        pctx, pwoT, bo, ptmp, NTOK, DMODEL, DMODEL);
    add_ln<<<NTOK, 256>>>(src, ptmp, ln1g, ln1b, px, pxr);

    // FFN1 (wide variant)
    gemm_mma<true, 2><<<dim3(DFF / 128, NTOK / 256), 512, SMEM_DYN>>>(
        pxr, pw1T, b1, pff, NTOK, DFF, DMODEL);
    // FFN2 (narrow variant: 256 blocks, 2/SM)
    gemm_mma128<false, 0><<<dim3(DMODEL / 128, NTOK / 128), 256, SMEM_DYN128>>>(
        pff, pw2T, b2, ptmp, NTOK, DMODEL, DFF);
    add_ln<<<NTOK, 256>>>(px, ptmp, ln2g, ln2b, out, (__half*)nullptr);
}